// round 1
// baseline (speedup 1.0000x reference)
#include <cuda_runtime.h>
#include <cuda_bf16.h>
#include <cstdint>

// RAPiD decode:
//   raw:    (nB=64, nA*6=18, nH=128, nW=128) fp32, channel-major
//   out:    (nB, nA*nH*nW, 6) fp32
// per pixel (b,a,h,w):
//   px = (sigmoid(r0)+w)/nW*img_w
//   py = (sigmoid(r1)+h)/nH*img_h
//   pw = exp(r2)*anchor_w[a]
//   ph = exp(r3)*anchor_h[a]
//   pa = sigmoid(r4)*360 - 180
//   conf = sigmoid(r5)

namespace {
constexpr int nB = 64;
constexpr int nA = 3;
constexpr int nH = 128;
constexpr int nW = 128;
constexpr int HW = nH * nW;           // 16384
constexpr int PAIRS_PER_SLICE = HW / 2;  // 8192
constexpr float ANGLE_RANGE = 360.0f;
}

__device__ __forceinline__ float fsigmoid(float x) {
    return __fdividef(1.0f, 1.0f + __expf(-x));
}

__global__ void __launch_bounds__(256)
rapid_decode_kernel(const float* __restrict__ raw,
                    const float* __restrict__ anchors,
                    const int* __restrict__ img_h_p,
                    const int* __restrict__ img_w_p,
                    float* __restrict__ out)
{
    // one thread = 2 consecutive pixels (same b,a,h; w0 even)
    const int t = blockIdx.x * blockDim.x + threadIdx.x;
    const int total = nB * nA * PAIRS_PER_SLICE;   // 1,572,864
    if (t >= total) return;

    const int slice  = t / PAIRS_PER_SLICE;        // b*nA + a
    const int within = t - slice * PAIRS_PER_SLICE;
    const int hw0 = within * 2;
    const int h   = hw0 >> 7;          // / nW
    const int w0  = hw0 & (nW - 1);

    const int b = slice / nA;
    const int a = slice - b * nA;

    const float img_h = img_h_p ? (float)__ldg(img_h_p) : 1024.0f;
    const float img_w = img_w_p ? (float)__ldg(img_w_p) : 1024.0f;
    const float sx = img_w * (1.0f / (float)nW);
    const float sy = img_h * (1.0f / (float)nH);

    const float aw = __ldg(&anchors[a * 2 + 0]);
    const float ah = __ldg(&anchors[a * 2 + 1]);

    // channel base: raw[(b*18 + a*6 + c)*HW + hw0]
    const float* base = raw + ((size_t)(b * (nA * 6) + a * 6) * HW + hw0);
    const float2 rx = *(const float2*)(base + 0 * HW);
    const float2 ry = *(const float2*)(base + 1 * HW);
    const float2 rw = *(const float2*)(base + 2 * HW);
    const float2 rh = *(const float2*)(base + 3 * HW);
    const float2 ra = *(const float2*)(base + 4 * HW);
    const float2 rc = *(const float2*)(base + 5 * HW);

    // pixel 0
    const float px0 = (fsigmoid(rx.x) + (float)w0) * sx;
    const float py0 = (fsigmoid(ry.x) + (float)h) * sy;
    const float pw0 = __expf(rw.x) * aw;
    const float ph0 = __expf(rh.x) * ah;
    const float pa0 = fsigmoid(ra.x) * ANGLE_RANGE - ANGLE_RANGE * 0.5f;
    const float pc0 = fsigmoid(rc.x);
    // pixel 1
    const float px1 = (fsigmoid(rx.y) + (float)(w0 + 1)) * sx;
    const float py1 = (fsigmoid(ry.y) + (float)h) * sy;
    const float pw1 = __expf(rw.y) * aw;
    const float ph1 = __expf(rh.y) * ah;
    const float pa1 = fsigmoid(ra.y) * ANGLE_RANGE - ANGLE_RANGE * 0.5f;
    const float pc1 = fsigmoid(rc.y);

    // out base: ((b*nA + a)*HW + hw0) * 6 elements — hw0 even => 48B aligned
    float* o = out + (size_t)(slice * (size_t)HW + hw0) * 6;
    ((float4*)o)[0] = make_float4(px0, py0, pw0, ph0);
    ((float4*)o)[1] = make_float4(pa0, pc0, px1, py1);
    ((float4*)o)[2] = make_float4(pw1, ph1, pa1, pc1);
}

extern "C" void kernel_launch(void* const* d_in, const int* in_sizes, int n_in,
                              void* d_out, int out_size)
{
    const float* raw     = (const float*)d_in[0];
    const float* anchors = (const float*)d_in[1];
    const int* img_h_p   = (n_in > 2) ? (const int*)d_in[2] : nullptr;
    const int* img_w_p   = (n_in > 3) ? (const int*)d_in[3] : nullptr;
    float* out = (float*)d_out;

    const int total = nB * nA * PAIRS_PER_SLICE;  // 1,572,864 threads
    const int block = 256;
    const int grid = (total + block - 1) / block; // 6144
    rapid_decode_kernel<<<grid, block>>>(raw, anchors, img_h_p, img_w_p, out);
}

// round 2
// speedup vs baseline: 1.0793x; 1.0793x over previous
#include <cuda_runtime.h>
#include <cuda_bf16.h>
#include <cstdint>

// RAPiD decode:
//   raw:    (nB=64, nA*6=18, nH=128, nW=128) fp32, channel-major
//   out:    (nB, nA*nH*nW, 6) fp32
// per pixel (b,a,h,w):
//   px = (sigmoid(r0)+w)/nW*img_w
//   py = (sigmoid(r1)+h)/nH*img_h
//   pw = exp(r2)*anchor_w[a]
//   ph = exp(r3)*anchor_h[a]
//   pa = sigmoid(r4)*360 - 180
//   conf = sigmoid(r5)
//
// R1 -> R2: warp-private smem store staging. The 48B/lane-stride STG.128s
// inflated L1 store wavefronts ~3x (L1=57.7% was the binding pipe). Each warp
// now stages its 64-pixel (1536B) output tile in smem (conflict-free both
// directions) and drains it with 3 perfectly-coalesced STG.128 rounds.

namespace {
constexpr int nB = 64;
constexpr int nA = 3;
constexpr int nH = 128;
constexpr int nW = 128;
constexpr int HW = nH * nW;              // 16384 pixels per (b,a) slice
constexpr int WARPS_PER_BLOCK = 8;
constexpr int PIX_PER_WARP = 64;         // 2 per lane
constexpr int PIX_PER_BLOCK = WARPS_PER_BLOCK * PIX_PER_WARP;  // 512
constexpr int BLOCKS_PER_SLICE = HW / PIX_PER_BLOCK;           // 32
constexpr float ANGLE_RANGE = 360.0f;
}

__device__ __forceinline__ float fsigmoid(float x) {
    return __fdividef(1.0f, 1.0f + __expf(-x));
}

__global__ void __launch_bounds__(256)
rapid_decode_kernel(const float* __restrict__ raw,
                    const float* __restrict__ anchors,
                    const int* __restrict__ img_h_p,
                    const int* __restrict__ img_w_p,
                    float* __restrict__ out)
{
    // 6 floats/pixel * 64 pixels/warp = 384 floats = 1536 B per warp
    __shared__ float stage[WARPS_PER_BLOCK * PIX_PER_WARP * 6];

    const int tid  = threadIdx.x;
    const int lane = tid & 31;
    const int warp = tid >> 5;

    // block-uniform slice / anchor math (no block straddles a slice)
    const int slice   = blockIdx.x >> 5;                     // / BLOCKS_PER_SLICE
    const int blk_in  = blockIdx.x & (BLOCKS_PER_SLICE - 1);
    const int b = slice / nA;
    const int a = slice - b * nA;

    const int warp_hw = blk_in * PIX_PER_BLOCK + warp * PIX_PER_WARP;
    const int hw0 = warp_hw + 2 * lane;                      // even
    const int h   = hw0 >> 7;                                // / nW
    const int w0  = hw0 & (nW - 1);

    const float img_h = img_h_p ? (float)__ldg(img_h_p) : 1024.0f;
    const float img_w = img_w_p ? (float)__ldg(img_w_p) : 1024.0f;
    const float sx = img_w * (1.0f / (float)nW);
    const float sy = img_h * (1.0f / (float)nH);

    const float aw = __ldg(&anchors[a * 2 + 0]);
    const float ah = __ldg(&anchors[a * 2 + 1]);

    // channel base: raw[(b*18 + a*6 + c)*HW + hw0] -- coalesced LDG.64 per channel
    const float* base = raw + ((size_t)(b * (nA * 6) + a * 6) * HW + hw0);
    const float2 rx = *(const float2*)(base + 0 * HW);
    const float2 ry = *(const float2*)(base + 1 * HW);
    const float2 rw = *(const float2*)(base + 2 * HW);
    const float2 rh = *(const float2*)(base + 3 * HW);
    const float2 ra = *(const float2*)(base + 4 * HW);
    const float2 rc = *(const float2*)(base + 5 * HW);

    // pixel 0
    const float px0 = (fsigmoid(rx.x) + (float)w0) * sx;
    const float py0 = (fsigmoid(ry.x) + (float)h) * sy;
    const float pw0 = __expf(rw.x) * aw;
    const float ph0 = __expf(rh.x) * ah;
    const float pa0 = fsigmoid(ra.x) * ANGLE_RANGE - ANGLE_RANGE * 0.5f;
    const float pc0 = fsigmoid(rc.x);
    // pixel 1
    const float px1 = (fsigmoid(rx.y) + (float)(w0 + 1)) * sx;
    const float py1 = (fsigmoid(ry.y) + (float)h) * sy;
    const float pw1 = __expf(rw.y) * aw;
    const float ph1 = __expf(rh.y) * ah;
    const float pa1 = fsigmoid(ra.y) * ANGLE_RANGE - ANGLE_RANGE * 0.5f;
    const float pc1 = fsigmoid(rc.y);

    // stage into warp-private smem: lane writes 12 contiguous floats at 48B/lane
    // (conflict-free: within each 8-lane phase, banks [12t..12t+3] mod 32 disjoint)
    float4* ws = (float4*)(stage + warp * (PIX_PER_WARP * 6));
    ws[3 * lane + 0] = make_float4(px0, py0, pw0, ph0);
    ws[3 * lane + 1] = make_float4(pa0, pc0, px1, py1);
    ws[3 * lane + 2] = make_float4(pw1, ph1, pa1, pc1);

    __syncwarp();

    // drain: warp's output region is 1536B contiguous -> 3 coalesced STG.128
    float4* og = (float4*)(out + ((size_t)slice * HW + warp_hw) * 6);
    og[lane +  0] = ws[lane +  0];
    og[lane + 32] = ws[lane + 32];
    og[lane + 64] = ws[lane + 64];
}

extern "C" void kernel_launch(void* const* d_in, const int* in_sizes, int n_in,
                              void* d_out, int out_size)
{
    const float* raw     = (const float*)d_in[0];
    const float* anchors = (const float*)d_in[1];
    const int* img_h_p   = (n_in > 2) ? (const int*)d_in[2] : nullptr;
    const int* img_w_p   = (n_in > 3) ? (const int*)d_in[3] : nullptr;
    float* out = (float*)d_out;

    const int grid = nB * nA * BLOCKS_PER_SLICE;   // 6144 blocks
    rapid_decode_kernel<<<grid, 256>>>(raw, anchors, img_h_p, img_w_p, out);
}